// round 5
// baseline (speedup 1.0000x reference)
#include <cuda_runtime.h>
#include <cuda_bf16.h>

// QFM: out[b] = sum_f linear_w[x[b,f]+f*V] + bias
//             + 0.5 * sum_d ( (sum_f emb[b,f,d])^2 - sum_f emb[b,f,d]^2 )
// B=16384, F=39, V=100000, D=128, K=256, M=8, Q=16.
//
// TWO warps per row: half 0 -> f=0..19, half 1 -> f=20..38.
// Lane t owns float4 #t of the 512B embedding (dims 4t..4t+3), m = t>>2.
// q (sum of squares) and lin are additive across the pair; only the per-dim
// sum s must be combined (via smem) before squaring.

constexpr int F = 39;
constexpr int V = 100000;
constexpr int K = 256;

__global__ __launch_bounds__(256, 5)   // <=51 regs, up to 40 warps/SM
void qfm_kernel(const int*    __restrict__ x,          // (B, F)
                const float4* __restrict__ codebooks,  // (F*K, 32) as float4
                const int*    __restrict__ cb_index,   // (F*V, 8)
                const float*  __restrict__ linear_w,   // (F*V)
                const float*  __restrict__ linear_bias,// (1)
                float*        __restrict__ out,        // (B)
                int B)
{
    const unsigned FULL = 0xffffffffu;
    __shared__ float4 sbuf[4][32];   // odd warp's per-lane s
    __shared__ float  pbuf[4];       // odd warp's scalar partial

    const int gwarp  = (blockIdx.x * blockDim.x + threadIdx.x) >> 5;
    const int lane   = threadIdx.x & 31;
    const int row    = gwarp >> 1;
    const int half   = gwarp & 1;            // 0: f<20, 1: f>=20
    const int pair   = (threadIdx.x >> 6);   // 0..3 row-pair within block
    const bool active = (row < B);

    const int base = half * 20;
    const int NF   = half ? (F - 20) : 20;   // 19 or 20

    // --- per-row indices for this half: lane k holds x[row, base+k]
    int idxr = 0;
    if (active && lane < NF) idxr = __ldcs(&x[row * F + base + lane]);

    // --- linear term (streaming, no reuse)
    float lin = 0.f;
    if (active && lane < NF) lin = __ldcs(&linear_w[(base + lane) * V + idxr]);

    // --- Phase A: all codes of this half via 5 independent coalesced LDGs.
    // Chunk c covers local features 4c..4c+3; lane L reads code (L&7) of
    // local feature 4c + (L>>3).
    int codes[5];
    const int sub = lane >> 3;
    const int mm  = lane & 7;
    #pragma unroll
    for (int c = 0; c < 5; ++c) {
        const int kl = 4 * c + sub;                 // local feature 0..19
        const int idxf = __shfl_sync(FULL, idxr, kl);
        codes[c] = 0;
        if (active && kl < NF)
            codes[c] = __ldcs(&cb_index[((base + kl) * V + idxf) * 8 + mm]);
    }

    // --- Phase B: up to 20 independent float4 gathers + FMA accumulation.
    const int m = lane >> 2;
    float4 s = make_float4(0.f, 0.f, 0.f, 0.f);
    float4 q = make_float4(0.f, 0.f, 0.f, 0.f);

    #pragma unroll
    for (int k = 0; k < 20; ++k) {
        if (k >= NF) break;                         // only trims k=19 on half 1
        const int src  = ((k & 3) << 3) | m;
        const int code = __shfl_sync(FULL, codes[k >> 2], src);
        if (active) {
            const float4 e = __ldg(&codebooks[((base + k) * K + code) * 32 + lane]);
            s.x += e.x; s.y += e.y; s.z += e.z; s.w += e.w;
            q.x = fmaf(e.x, e.x, q.x);
            q.y = fmaf(e.y, e.y, q.y);
            q.z = fmaf(e.z, e.z, q.z);
            q.w = fmaf(e.w, e.w, q.w);
        }
    }

    // Scalar additive part of this warp: lin - 0.5 * sum(q)
    float p = lin - 0.5f * (q.x + q.y + q.z + q.w);

    if (half == 1) {
        // publish s and reduced scalar partial
        sbuf[pair][lane] = s;
        #pragma unroll
        for (int o = 16; o > 0; o >>= 1)
            p += __shfl_xor_sync(FULL, p, o);
        if (lane == 0) pbuf[pair] = p;
    }
    __syncthreads();

    if (half == 0 && active) {
        const float4 s2 = sbuf[pair][lane];
        const float ax = s.x + s2.x, ay = s.y + s2.y;
        const float az = s.z + s2.z, aw = s.w + s2.w;
        float t = 0.5f * (ax * ax + ay * ay + az * az + aw * aw) + p;
        #pragma unroll
        for (int o = 16; o > 0; o >>= 1)
            t += __shfl_xor_sync(FULL, t, o);
        if (lane == 0)
            out[row] = t + pbuf[pair] + __ldg(linear_bias);
    }
}

extern "C" void kernel_launch(void* const* d_in, const int* in_sizes, int n_in,
                              void* d_out, int out_size)
{
    const int*    x         = (const int*)   d_in[0];
    const float4* codebooks = (const float4*)d_in[1];
    const int*    cb_index  = (const int*)   d_in[2];
    const float*  linear_w  = (const float*) d_in[3];
    const float*  lbias     = (const float*) d_in[4];
    float*        out       = (float*)       d_out;

    const int B = out_size;
    const int threads = 256;                          // 8 warps = 4 rows/block
    const long long total_threads = (long long)B * 2 * 32;
    const int blocks = (int)((total_threads + threads - 1) / threads);
    qfm_kernel<<<blocks, threads>>>(x, codebooks, cb_index, linear_w, lbias, out, B);
}

// round 7
// speedup vs baseline: 1.0685x; 1.0685x over previous
#include <cuda_runtime.h>
#include <cuda_fp16.h>

// QFM: out[b] = sum_f linear_w[x[b,f]+f*V] + bias
//             + 0.5 * sum_d ( (sum_f emb[b,f,d])^2 - sum_f emb[b,f,d]^2 )
// B=16384, F=39, V=100000, D=128, K=256, M=8, Q=16.
//
// R6: codebooks converted once per launch to fp16 (prologue kernel) ->
// codebook gather traffic/wavefronts halve (512B -> 256B per row).
// Main kernel = R3 structure: one warp per row, lane t owns dims 4t..4t+3
// (m = t>>2); all 39 gathers independent (codes prefetched via 10 coalesced
// LDGs), fp32 accumulation.

constexpr int F = 39;
constexpr int V = 100000;
constexpr int K = 256;
constexpr int D = 128;
constexpr int CB4 = F * K * D / 4;     // 319488 uint2 (4 halfs each)

__device__ uint2 g_cbh[CB4];           // fp16 codebooks, 2.56 MB scratch

__device__ __forceinline__ unsigned h2_bits(__half2 h) {
    return *reinterpret_cast<unsigned*>(&h);
}
__device__ __forceinline__ __half2 bits_h2(unsigned u) {
    return *reinterpret_cast<__half2*>(&u);
}

__global__ __launch_bounds__(256)
void cvt_kernel(const float4* __restrict__ src)
{
    const int i = blockIdx.x * blockDim.x + threadIdx.x;
    if (i < CB4) {
        const float4 v = src[i];
        uint2 o;
        o.x = h2_bits(__floats2half2_rn(v.x, v.y));
        o.y = h2_bits(__floats2half2_rn(v.z, v.w));
        g_cbh[i] = o;
    }
}

__global__ __launch_bounds__(256, 4)   // <=64 regs, 32 warps/SM
void qfm_kernel(const int*    __restrict__ x,          // (B, F)
                const int*    __restrict__ cb_index,   // (F*V, 8)
                const float*  __restrict__ linear_w,   // (F*V)
                const float*  __restrict__ linear_bias,// (1)
                float*        __restrict__ out,        // (B)
                int B)
{
    const unsigned FULL = 0xffffffffu;
    const int warp = (blockIdx.x * blockDim.x + threadIdx.x) >> 5;
    const int lane = threadIdx.x & 31;
    if (warp >= B) return;

    const int* xrow = x + warp * F;

    // Row indices: lanes 0..31 hold f=0..31, lanes 0..6 hold f=32..38.
    const int idx_lo = __ldcs(&xrow[lane]);
    const int idx_hi = (lane < F - 32) ? __ldcs(&xrow[32 + lane]) : 0;

    // Linear term (streaming, no reuse).
    float lin = __ldcs(&linear_w[lane * V + idx_lo]);
    if (lane < F - 32) lin += __ldcs(&linear_w[(32 + lane) * V + idx_hi]);

    // Phase A: all 39x8 codes via 10 independent coalesced LDGs.
    // Chunk c covers features 4c..4c+3; lane L reads code (L&7) of
    // feature 4c + (L>>3).
    int codes[10];
    const int sub = lane >> 3;
    const int mm  = lane & 7;
    #pragma unroll
    for (int c = 0; c < 10; ++c) {
        const int fl = 4 * c + sub;
        int idxf;
        if (c < 8) idxf = __shfl_sync(FULL, idx_lo, fl);
        else       idxf = __shfl_sync(FULL, idx_hi, fl - 32);
        codes[c] = 0;
        if (fl < F) {
            const long long xo = (long long)fl * V + idxf;
            codes[c] = __ldcs(&cb_index[xo * 8 + mm]);
        }
    }

    // Phase B: 39 independent 8B fp16 gathers + fp32 FMA accumulation.
    const int m = lane >> 2;     // this lane's sub-codebook (dims 4t..4t+3)
    float4 s = make_float4(0.f, 0.f, 0.f, 0.f);
    float4 q = make_float4(0.f, 0.f, 0.f, 0.f);

    #pragma unroll
    for (int f = 0; f < F; ++f) {
        const int src  = ((f & 3) << 3) | m;            // lane holding code(f, m)
        const int code = __shfl_sync(FULL, codes[f >> 2], src);
        const uint2 raw = __ldg(&g_cbh[(f * K + code) * 32 + lane]);
        const float2 e0 = __half22float2(bits_h2(raw.x));
        const float2 e1 = __half22float2(bits_h2(raw.y));
        s.x += e0.x; s.y += e0.y; s.z += e1.x; s.w += e1.y;
        q.x = fmaf(e0.x, e0.x, q.x);
        q.y = fmaf(e0.y, e0.y, q.y);
        q.z = fmaf(e1.x, e1.x, q.z);
        q.w = fmaf(e1.y, e1.y, q.w);
    }

    float t = 0.5f * (fmaf(s.x, s.x, -q.x) +
                      fmaf(s.y, s.y, -q.y) +
                      fmaf(s.z, s.z, -q.z) +
                      fmaf(s.w, s.w, -q.w));
    t += lin;

    #pragma unroll
    for (int o = 16; o > 0; o >>= 1)
        t += __shfl_xor_sync(FULL, t, o);

    if (lane == 0) out[warp] = t + __ldg(linear_bias);
}

extern "C" void kernel_launch(void* const* d_in, const int* in_sizes, int n_in,
                              void* d_out, int out_size)
{
    const int*    x         = (const int*)   d_in[0];
    const float4* codebooks = (const float4*)d_in[1];
    const int*    cb_index  = (const int*)   d_in[2];
    const float*  linear_w  = (const float*) d_in[3];
    const float*  lbias     = (const float*) d_in[4];
    float*        out       = (float*)       d_out;

    const int B = out_size;

    // Prologue: fp32 -> fp16 codebook conversion (L2-resident, ~1-2 us).
    cvt_kernel<<<(CB4 + 255) / 256, 256>>>(codebooks);

    const int threads = 256;                       // 8 warps/block, 1 warp/row
    const int blocks  = (B * 32 + threads - 1) / threads;
    qfm_kernel<<<blocks, threads>>>(x, cb_index, linear_w, lbias, out, B);
}